// round 1
// baseline (speedup 1.0000x reference)
#include <cuda_runtime.h>

#define N_EMIT  512
#define ZPL     8
#define ROI     20
#define SPL_D   64
#define SPL_H   40
#define SPL_W   40

__global__ __launch_bounds__(128) void psf_kernel(
    const float* __restrict__ pos,
    const float* __restrict__ inten,
    const float* __restrict__ bg,
    const float* __restrict__ coefs,
    float* __restrict__ out)
{
    const int b   = blockIdx.x;
    const int z   = b >> 9;     // blockIdx = z*512 + n  (same-z blocks adjacent -> L1 reuse)
    const int n   = b & 511;
    const int tid = threadIdx.x;

    __shared__ float sdy[ROI], sdx[ROI];
    __shared__ int   siy[ROI], six[ROI];
    __shared__ float swarp[4];
    __shared__ float sscale;

    const float p0 = pos[n * 3 + 0];   // used for Y axis (faithful to reference)
    const float p1 = pos[n * 3 + 1];   // used for X axis
    const float p2 = pos[n * 3 + 2];   // used for Z axis

    // Per-row / per-col fractional parts and cell indices, computed exactly
    // as the reference does per point: ((float)coord - pos) + const, then floor.
    if (tid < ROI) {
        float pyf = ((float)tid - p0) + 10.0f;   // SPL_H/2 - ROI/2 = 10
        float fy  = floorf(pyf);
        sdy[tid]  = pyf - fy;
        int iy    = (int)fy;
        siy[tid]  = max(0, min(iy, SPL_H - 1));
    } else if (tid >= 32 && tid < 32 + ROI) {
        int   x   = tid - 32;
        float pxf = ((float)x - p1) + 10.0f;     // SPL_W/2 - ROI/2 = 10
        float fx  = floorf(pxf);
        sdx[x]    = pxf - fx;
        int ix    = (int)fx;
        six[x]    = max(0, min(ix, SPL_W - 1));
    }

    // z-direction (constant for this block)
    float pzf = ((float)z - p2) + 28.0f;         // SPL_D/2 - ZPL/2 = 28
    float fz  = floorf(pzf);
    float dz  = pzf - fz;
    int   iz  = (int)fz;
    iz = max(0, min(iz, SPL_D - 1));

    __syncthreads();

    float vals[4];
    float tsum = 0.0f;

    #pragma unroll
    for (int i = 0; i < 4; i++) {
        int p   = tid + i * 128;
        vals[i] = 0.0f;
        if (p < ROI * ROI) {
            int y = p / 20;
            int x = p - y * 20;
            float dy = sdy[y], dx = sdx[x];
            int   iy = siy[y], ix = six[x];

            const float4* cp = (const float4*)(coefs +
                ((((size_t)iz * SPL_H + iy) * SPL_W + ix) << 6));

            float dx2 = dx * dx, dx3 = dx2 * dx;
            float dy2 = dy * dy, dy3 = dy2 * dy;

            float s[4];
            #pragma unroll
            for (int a = 0; a < 4; a++) {
                float4 c0 = cp[a * 4 + 0];
                float4 c1 = cp[a * 4 + 1];
                float4 c2 = cp[a * 4 + 2];
                float4 c3 = cp[a * 4 + 3];
                float t0 = fmaf(c0.w, dx3, fmaf(c0.z, dx2, fmaf(c0.y, dx, c0.x)));
                float t1 = fmaf(c1.w, dx3, fmaf(c1.z, dx2, fmaf(c1.y, dx, c1.x)));
                float t2 = fmaf(c2.w, dx3, fmaf(c2.z, dx2, fmaf(c2.y, dx, c2.x)));
                float t3 = fmaf(c3.w, dx3, fmaf(c3.z, dx2, fmaf(c3.y, dx, c3.x)));
                s[a] = fmaf(t3, dy3, fmaf(t2, dy2, fmaf(t1, dy, t0)));
            }
            float v = fmaf(fmaf(fmaf(s[3], dz, s[2]), dz, s[1]), dz, s[0]);
            vals[i] = v;
            tsum   += v;
        }
    }

    // Block reduction over 128 threads (4 warps)
    #pragma unroll
    for (int off = 16; off > 0; off >>= 1)
        tsum += __shfl_down_sync(0xffffffffu, tsum, off);
    if ((tid & 31) == 0) swarp[tid >> 5] = tsum;
    __syncthreads();
    if (tid == 0) {
        float total = (swarp[0] + swarp[1]) + (swarp[2] + swarp[3]);
        sscale = inten[n * ZPL + z] / total;
    }
    __syncthreads();

    const float scale = sscale;
    const float bgv   = bg[n * ZPL + z];
    float* op = out + ((size_t)n * ZPL + z) * (ROI * ROI);

    #pragma unroll
    for (int i = 0; i < 4; i++) {
        int p = tid + i * 128;
        if (p < ROI * ROI) op[p] = fmaf(vals[i], scale, bgv);
    }
}

extern "C" void kernel_launch(void* const* d_in, const int* in_sizes, int n_in,
                              void* d_out, int out_size)
{
    const float* pos   = (const float*)d_in[0];
    const float* inten = (const float*)d_in[1];
    const float* bg    = (const float*)d_in[2];
    const float* coefs = (const float*)d_in[3];
    psf_kernel<<<N_EMIT * ZPL, 128>>>(pos, inten, bg, coefs, (float*)d_out);
}

// round 2
// speedup vs baseline: 2.1844x; 2.1844x over previous
#include <cuda_runtime.h>

#define N_EMIT  512
#define ZPL     8
#define ROI     20
#define SPL_D   64
#define SPL_H   40
#define SPL_W   40

__global__ __launch_bounds__(128) void psf_kernel(
    const float* __restrict__ pos,
    const float* __restrict__ inten,
    const float* __restrict__ bg,
    const float* __restrict__ coefs,
    float* __restrict__ out)
{
    const int b    = blockIdx.x;
    const int z    = b >> 9;          // blockIdx = z*512 + n (same-z blocks adjacent -> L1 reuse)
    const int n    = b & 511;
    const int tid  = threadIdx.x;
    const int warp = tid >> 5;
    const int lane = tid & 31;
    const int sub  = lane >> 4;       // which of 2 pixels in this warp-round
    const int j    = lane & 15;       // which float4 of the 64-coef cell

    __shared__ float4 sypow[ROI];     // {1, dy, dy^2, dy^3} per row (exact per-row values)
    __shared__ float4 sxpow[ROI];     // {1, dx, dx^2, dx^3} per col
    __shared__ int    srow[ROI];      // (iz*40 + iy)*40  per row
    __shared__ int    six[ROI];       // ix per col
    __shared__ float  sPlane[ROI * ROI];
    __shared__ float  swarp[4];
    __shared__ float  sscale;

    const float p0 = pos[n * 3 + 0];  // Y axis (faithful to reference)
    const float p1 = pos[n * 3 + 1];  // X axis
    const float p2 = pos[n * 3 + 2];  // Z axis

    // z-direction (constant for this block) — same expression order as reference
    float pzf = ((float)z - p2) + 28.0f;       // SPL_D/2 - ZPLANES/2
    float fz  = floorf(pzf);
    float dz  = pzf - fz;
    int   iz  = max(0, min((int)fz, SPL_D - 1));

    // Per-row / per-col tables, bit-faithful per coordinate
    if (tid < ROI) {
        float pyf = ((float)tid - p0) + 10.0f; // SPL_H/2 - ROI/2
        float fy  = floorf(pyf);
        float dy  = pyf - fy;
        int   iy  = max(0, min((int)fy, SPL_H - 1));
        float dy2 = dy * dy;
        sypow[tid] = make_float4(1.0f, dy, dy2, dy2 * dy);
        srow[tid]  = (iz * SPL_H + iy) * SPL_W;
    } else if (tid >= 32 && tid < 32 + ROI) {
        int   x   = tid - 32;
        float pxf = ((float)x - p1) + 10.0f;   // SPL_W/2 - ROI/2
        float fx  = floorf(pxf);
        float dx  = pxf - fx;
        int   ix  = max(0, min((int)fx, SPL_W - 1));
        float dx2 = dx * dx;
        sxpow[x]  = make_float4(1.0f, dx, dx2, dx2 * dx);
        six[x]    = ix;
    }
    __syncthreads();

    // Per-lane z-weight: dz^a with a = j>>2
    const int   a   = j >> 2;
    const float dz2 = dz * dz;
    const float wz  = (a & 1 ? dz : 1.0f) * (a & 2 ? dz2 : 1.0f);
    const int   bsel = j & 3;          // y-exponent for this lane

    float tsum = 0.0f;

    // Each warp owns 5 rows; 10 rounds of 2 pixels per row.
    #pragma unroll
    for (int rr = 0; rr < 5; rr++) {
        const int y = warp + rr * 4;
        // per-row constants (broadcast LDS)
        const float wy   = ((const float*)&sypow[y])[bsel];
        const float wyz  = wz * wy;
        const float* rowp = coefs + (size_t)srow[y] * 64;

        #pragma unroll
        for (int r = 0; r < 10; r++) {
            const int x  = r * 2 + sub;
            const int ix = six[x];
            const float4 xp = sxpow[x];
            const float4 c  = *(const float4*)(rowp + ((size_t)ix << 6) + (j << 2));

            float partial = fmaf(c.w, xp.w, fmaf(c.z, xp.z, fmaf(c.y, xp.y, c.x)));
            partial *= wyz;

            // reduce over the 16 lanes of this half-warp
            partial += __shfl_xor_sync(0xffffffffu, partial, 8);
            partial += __shfl_xor_sync(0xffffffffu, partial, 4);
            partial += __shfl_xor_sync(0xffffffffu, partial, 2);
            partial += __shfl_xor_sync(0xffffffffu, partial, 1);

            if (j == 0) {
                sPlane[y * ROI + x] = partial;
                tsum += partial;
            }
        }
    }

    // Block reduction (only j==0 lanes hold nonzero tsum; zeros elsewhere are harmless)
    #pragma unroll
    for (int off = 16; off > 0; off >>= 1)
        tsum += __shfl_down_sync(0xffffffffu, tsum, off);
    if (lane == 0) swarp[warp] = tsum;
    __syncthreads();
    if (tid == 0) {
        float total = (swarp[0] + swarp[1]) + (swarp[2] + swarp[3]);
        sscale = inten[n * ZPL + z] / total;
    }
    __syncthreads();

    const float scale = sscale;
    const float bgv   = bg[n * ZPL + z];
    float* op = out + ((size_t)n * ZPL + z) * (ROI * ROI);

    #pragma unroll
    for (int i = 0; i < 4; i++) {
        int p = tid + i * 128;
        if (p < ROI * ROI) op[p] = fmaf(sPlane[p], scale, bgv);
    }
}

extern "C" void kernel_launch(void* const* d_in, const int* in_sizes, int n_in,
                              void* d_out, int out_size)
{
    const float* pos   = (const float*)d_in[0];
    const float* inten = (const float*)d_in[1];
    const float* bg    = (const float*)d_in[2];
    const float* coefs = (const float*)d_in[3];
    psf_kernel<<<N_EMIT * ZPL, 128>>>(pos, inten, bg, coefs, (float*)d_out);
}

// round 3
// speedup vs baseline: 4.0869x; 1.8709x over previous
#include <cuda_runtime.h>

#define N_EMIT  512
#define ZPL     8
#define ROI     20
#define SPL_D   64
#define SPL_H   40
#define SPL_W   40
#define PITCH   420   // words; 420 mod 32 == 4 -> STS banks 4j+g all distinct

__global__ __launch_bounds__(128, 8) void psf_kernel(
    const float* __restrict__ pos,
    const float* __restrict__ inten,
    const float* __restrict__ bg,
    const float* __restrict__ coefs,
    float* __restrict__ out)
{
    const int b    = blockIdx.x;
    const int z    = b >> 9;          // blockIdx = z*512 + n (same-z blocks adjacent -> L1 reuse)
    const int n    = b & 511;
    const int tid  = threadIdx.x;
    const int warp = tid >> 5;
    const int lane = tid & 31;
    const int j    = lane & 7;        // coef slot within pixel (float4 #j and #j+8)
    const int g    = lane >> 3;       // pixel within group of 4

    __shared__ float4 sxpow[ROI];     // {1, dx, dx^2, dx^3}
    __shared__ float  sypow[ROI][4];  // {1, dy, dy^2, dy^3}
    __shared__ int    srowoff[ROI];   // float offset of (iz,iy) row base
    __shared__ int    scoloff[ROI];   // ix*64
    __shared__ float  sP[8 * PITCH];  // per-pixel partials, j-major
    __shared__ float  swarp[4];
    __shared__ float  sscale;

    const float p0 = pos[n * 3 + 0];  // Y axis (faithful to reference)
    const float p1 = pos[n * 3 + 1];  // X axis
    const float p2 = pos[n * 3 + 2];  // Z axis

    // z-direction (constant for this block) — same expression order as reference
    float pzf = ((float)z - p2) + 28.0f;        // SPL_D/2 - ZPLANES/2
    float fz  = floorf(pzf);
    float dz  = pzf - fz;
    int   iz  = max(0, min((int)fz, SPL_D - 1));

    if (tid < ROI) {
        float pyf = ((float)tid - p0) + 10.0f;  // SPL_H/2 - ROI/2
        float fy  = floorf(pyf);
        float dy  = pyf - fy;
        int   iy  = max(0, min((int)fy, SPL_H - 1));
        float dy2 = dy * dy;
        sypow[tid][0] = 1.0f;
        sypow[tid][1] = dy;
        sypow[tid][2] = dy2;
        sypow[tid][3] = dy2 * dy;
        srowoff[tid]  = ((iz * SPL_H + iy) * SPL_W) << 6;
    } else if (tid >= 32 && tid < 32 + ROI) {
        int   x   = tid - 32;
        float pxf = ((float)x - p1) + 10.0f;    // SPL_W/2 - ROI/2
        float fx  = floorf(pxf);
        float dx  = pxf - fx;
        int   ix  = max(0, min((int)fx, SPL_W - 1));
        float dx2 = dx * dx;
        sxpow[x]   = make_float4(1.0f, dx, dx2, dx2 * dx);
        scoloff[x] = ix << 6;
    }
    __syncthreads();

    // lane z-weights: float4 #j has a=j>>2, #j+8 has a=(j>>2)+2
    const float dz2 = dz * dz;
    const float wz0 = (j & 4) ? dz : 1.0f;
    const float wz1 = wz0 * dz2;
    const int   bsel = j & 3;

    float nsum = 0.0f;

    // Each warp owns 5 rows; each round handles 4 pixels (g) of one row.
    for (int rr = 0; rr < 5; rr++) {
        const int   y      = warp * 5 + rr;
        const float wy     = sypow[y][bsel];
        const int   rowoff = srowoff[y];
        const float wzy0   = wz0 * wy;
        const float wzy1   = wz1 * wy;
        const int   pxrow  = y * ROI;

        #pragma unroll
        for (int r = 0; r < 5; r++) {
            const int    x  = r * 4 + g;
            const float4 xp = sxpow[x];
            const float* cp = coefs + rowoff + scoloff[x] + (j << 2);
            const float4 c0 = *(const float4*)cp;
            const float4 c1 = *(const float4*)(cp + 32);

            float d0 = fmaf(c0.w, xp.w, fmaf(c0.z, xp.z, fmaf(c0.y, xp.y, c0.x)));
            float d1 = fmaf(c1.w, xp.w, fmaf(c1.z, xp.z, fmaf(c1.y, xp.y, c1.x)));
            float partial = fmaf(wzy1, d1, wzy0 * d0);

            sP[j * PITCH + pxrow + x] = partial;   // conflict-free STS
            nsum += partial;
        }
    }

    // Block reduction of nsum (sum of ALL partials = plane total)
    #pragma unroll
    for (int off = 16; off > 0; off >>= 1)
        nsum += __shfl_down_sync(0xffffffffu, nsum, off);
    if (lane == 0) swarp[warp] = nsum;
    __syncthreads();
    if (tid == 0) {
        float total = (swarp[0] + swarp[1]) + (swarp[2] + swarp[3]);
        sscale = inten[n * ZPL + z] / total;
    }
    __syncthreads();

    const float scale = sscale;
    const float bgv   = bg[n * ZPL + z];
    float* op = out + ((size_t)n * ZPL + z) * (ROI * ROI);

    #pragma unroll
    for (int i = 0; i < 4; i++) {
        int p = tid + i * 128;
        if (p < ROI * ROI) {
            float v0 = sP[0 * PITCH + p] + sP[1 * PITCH + p];
            float v1 = sP[2 * PITCH + p] + sP[3 * PITCH + p];
            float v2 = sP[4 * PITCH + p] + sP[5 * PITCH + p];
            float v3 = sP[6 * PITCH + p] + sP[7 * PITCH + p];
            float v  = (v0 + v1) + (v2 + v3);
            op[p] = fmaf(v, scale, bgv);
        }
    }
}

extern "C" void kernel_launch(void* const* d_in, const int* in_sizes, int n_in,
                              void* d_out, int out_size)
{
    const float* pos   = (const float*)d_in[0];
    const float* inten = (const float*)d_in[1];
    const float* bg    = (const float*)d_in[2];
    const float* coefs = (const float*)d_in[3];
    psf_kernel<<<N_EMIT * ZPL, 128>>>(pos, inten, bg, coefs, (float*)d_out);
}